// round 17
// baseline (speedup 1.0000x reference)
#include <cuda_runtime.h>
#include <cuda_fp16.h>
#include <cstdint>

#define BB 8
#define CC 256
#define NN 4096
#define EPSV 1e-5f
#define L2E 1.4426950408889634f

// ---------------- device-global scratch ----------------
__device__ __half g_Wqk_h[64 * CC];                // [o][c] fp16 hi
__device__ __half g_Wqk_l[64 * CC];                // [o][c] fp16 lo
__device__ __half g_Wv[CC * CC];                   // [c_out][c_in] fp16
__device__ float  g_Beff[320];
__device__ __half g_xT[(size_t)BB * NN * CC];      // [b][n][c] fp16
__device__ __half g_Qt[(size_t)BB * NN * 64];      // [b][n][hi32|pad32]
__device__ __half g_Kt[(size_t)BB * NN * 64];      // [b][n][hi32|pad32]
__device__ __half g_V [(size_t)BB * CC * NN];      // [b][c][n] fp16
__device__ float  g_Qn[(size_t)BB * NN];           // |q_i| per row
__device__ unsigned g_Kmax[BB];                    // max_j |k_j| per batch

// ---------------- helpers ----------------
__device__ __forceinline__ uint32_t sm_u32(const void* p) {
    uint32_t a;
    asm("{ .reg .u64 t; cvta.to.shared.u64 t, %1; cvt.u32.u64 %0, t; }" : "=r"(a) : "l"(p));
    return a;
}
__device__ __forceinline__ void mma16816(float* d, const uint32_t* a, const uint32_t* b) {
    asm volatile(
        "mma.sync.aligned.m16n8k16.row.col.f32.f16.f16.f32 "
        "{%0,%1,%2,%3}, {%4,%5,%6,%7}, {%8,%9}, {%0,%1,%2,%3};"
        : "+f"(d[0]), "+f"(d[1]), "+f"(d[2]), "+f"(d[3])
        : "r"(a[0]), "r"(a[1]), "r"(a[2]), "r"(a[3]), "r"(b[0]), "r"(b[1]));
}
__device__ __forceinline__ void mma16816z(float* d, const uint32_t* a, const uint32_t* b) {
    asm volatile(
        "mma.sync.aligned.m16n8k16.row.col.f32.f16.f16.f32 "
        "{%0,%1,%2,%3}, {%4,%5,%6,%7}, {%8,%9}, {%10,%11,%12,%13};"
        : "=f"(d[0]), "=f"(d[1]), "=f"(d[2]), "=f"(d[3])
        : "r"(a[0]), "r"(a[1]), "r"(a[2]), "r"(a[3]), "r"(b[0]), "r"(b[1]),
          "f"(0.f), "f"(0.f), "f"(0.f), "f"(0.f));
}
__device__ __forceinline__ void ldsm_x4(uint32_t* r, uint32_t addr) {
    asm volatile("ldmatrix.sync.aligned.m8n8.x4.shared.b16 {%0,%1,%2,%3}, [%4];"
        : "=r"(r[0]), "=r"(r[1]), "=r"(r[2]), "=r"(r[3]) : "r"(addr));
}
__device__ __forceinline__ void ldsm_x2(uint32_t* r, uint32_t addr) {
    asm volatile("ldmatrix.sync.aligned.m8n8.x2.shared.b16 {%0,%1}, [%2];"
        : "=r"(r[0]), "=r"(r[1]) : "r"(addr));
}
__device__ __forceinline__ uint32_t tile_addr(uint32_t base, int row, int ch) {
    return base + row * 128 + (((ch) ^ (row & 7)) << 4);
}
__device__ __forceinline__ uint32_t tile_addr256(uint32_t base, int row, int ch) {
    return base + row * 256 + (((((ch) & 7) ^ (row & 7)) | ((ch) & 8)) << 4);
}
__device__ __forceinline__ void cpasync16(uint32_t dst, const void* src) {
    asm volatile("cp.async.cg.shared.global [%0], [%1], 16;" :: "r"(dst), "l"(src) : "memory");
}
__device__ __forceinline__ uint32_t packh2(float lo, float hi) {
    uint32_t r; asm("cvt.rn.f16x2.f32 %0, %1, %2;" : "=r"(r) : "f"(hi), "f"(lo)); return r;
}
__device__ __forceinline__ uint32_t ex2h2(uint32_t a) {
    uint32_t r; asm("ex2.approx.f16x2 %0, %1;" : "=r"(r) : "r"(a)); return r;
}

// ---------------- 1) fold BN into conv ----------------
__global__ void fold_kernel(
    const float* __restrict__ wq, const float* __restrict__ bq,
    const float* __restrict__ gq, const float* __restrict__ betaq,
    const float* __restrict__ mq, const float* __restrict__ vq,
    const float* __restrict__ wk, const float* __restrict__ bk,
    const float* __restrict__ gk, const float* __restrict__ betak,
    const float* __restrict__ mk, const float* __restrict__ vk,
    const float* __restrict__ wv, const float* __restrict__ bv,
    const float* __restrict__ gv, const float* __restrict__ betav,
    const float* __restrict__ mv, const float* __restrict__ vv)
{
    int o = blockIdx.x, c = threadIdx.x;
    if (o == 0 && c < BB) g_Kmax[c] = 0u;
    const float *w, *bb, *g, *beta, *mean, *var;
    int oo;
    if (o < 32)      { w = wq; bb = bq; g = gq; beta = betaq; mean = mq; var = vq; oo = o; }
    else if (o < 64) { w = wk; bb = bk; g = gk; beta = betak; mean = mk; var = vk; oo = o - 32; }
    else             { w = wv; bb = bv; g = gv; beta = betav; mean = mv; var = vv; oo = o - 64; }
    float scale = g[oo] * rsqrtf(var[oo] + EPSV);
    float val = w[oo * CC + c] * scale;
    if (o < 64) {
        __half h = __float2half(val);
        g_Wqk_h[o * CC + c] = h;
        g_Wqk_l[o * CC + c] = __float2half(val - __half2float(h));
    } else {
        g_Wv[(o - 64) * CC + c] = __float2half(val);
    }
    if (c == 0) g_Beff[o] = (bb[oo] - mean[oo]) * scale + beta[oo];
}

// ---------------- 2) MMA QK conv + x^T pack + row norms ----------------
// dyn smem: xf 64x133 f32 (34048) | Ah 16384 | Al 16384 | Bh 8192 | Bl 8192 = 83200
__global__ void __launch_bounds__(256) qkconv_kernel(const float* __restrict__ x)
{
    extern __shared__ __align__(128) unsigned char qsm[];
    float* xf = (float*)qsm;
    const uint32_t sAh = sm_u32(qsm) + 34048;
    const uint32_t sAl = sAh + 16384;
    const uint32_t sBh = sAl + 16384;
    const uint32_t sBl = sBh + 8192;

    const int tid = threadIdx.x, wid = tid >> 5, lane = tid & 31;
    const int n0 = blockIdx.x * 128;
    const int b  = blockIdx.y;
    const float* xb = x + (size_t)b * CC * NN;

    float acc[8][4] = {};

    for (int kc = 0; kc < 4; kc++) {
        __syncthreads();
        #pragma unroll
        for (int l = 0; l < 32; l++) {
            int idx = tid + l * 256;
            int c = idx >> 7, n = idx & 127;
            xf[c * 133 + n] = xb[(size_t)(kc * 64 + c) * NN + n0 + n];
        }
        #pragma unroll
        for (int l = 0; l < 2; l++) {
            int idx = tid + l * 256;
            int row = idx >> 3, ch = idx & 7;
            uint4 vh = *(const uint4*)&g_Wqk_h[(size_t)row * CC + kc * 64 + ch * 8];
            uint4 vl = *(const uint4*)&g_Wqk_l[(size_t)row * CC + kc * 64 + ch * 8];
            *(uint4*)(qsm + (tile_addr(sBh, row, ch) - sm_u32(qsm))) = vh;
            *(uint4*)(qsm + (tile_addr(sBl, row, ch) - sm_u32(qsm))) = vl;
        }
        __syncthreads();

        #pragma unroll
        for (int l = 0; l < 4; l++) {
            int w = tid + l * 256;
            int n = w >> 3, cg = w & 7;
            __align__(16) __half hh[8], ll[8];
            #pragma unroll
            for (int e = 0; e < 8; e++) {
                float v = xf[(cg * 8 + e) * 133 + n];
                __half h = __float2half(v);
                hh[e] = h;
                ll[e] = __float2half(v - __half2float(h));
            }
            *(uint4*)(qsm + (tile_addr(sAh, n, cg) - sm_u32(qsm))) = *(uint4*)hh;
            *(uint4*)(qsm + (tile_addr(sAl, n, cg) - sm_u32(qsm))) = *(uint4*)ll;
            *(uint4*)&g_xT[((size_t)b * NN + n0 + n) * CC + kc * 64 + cg * 8] = *(uint4*)hh;
        }
        __syncthreads();

        #pragma unroll
        for (int ks = 0; ks < 4; ks++) {
            uint32_t ah[4], al[4];
            ldsm_x4(ah, tile_addr(sAh, wid * 16 + (lane & 15), ks * 2 + (lane >> 4)));
            ldsm_x4(al, tile_addr(sAl, wid * 16 + (lane & 15), ks * 2 + (lane >> 4)));
            #pragma unroll
            for (int of = 0; of < 8; of++) {
                int t = lane & 15;
                uint32_t bh[2], bl[2];
                ldsm_x2(bh, tile_addr(sBh, of * 8 + (t & 7), ks * 2 + (t >> 3)));
                ldsm_x2(bl, tile_addr(sBl, of * 8 + (t & 7), ks * 2 + (t >> 3)));
                mma16816(acc[of], ah, bh);
                mma16816(acc[of], ah, bl);
                mma16816(acc[of], al, bh);
            }
        }
    }

    const int r = lane >> 2, cq = (lane & 3) * 2;
    const int row0 = wid * 16 + r, row1 = row0 + 8;
    const size_t rb0 = ((size_t)b * NN + n0 + row0) * 64;
    const size_t rb1 = ((size_t)b * NN + n0 + row1) * 64;
    float sq0 = 0.f, sq1 = 0.f, sk0 = 0.f, sk1 = 0.f;
    #pragma unroll
    for (int of = 0; of < 8; of++) {
        int o = of * 8 + cq;
        float b0 = g_Beff[o], b1 = g_Beff[o + 1];
        float v0 = fmaxf(acc[of][0] + b0, 0.f);
        float v1 = fmaxf(acc[of][1] + b1, 0.f);
        float v2 = fmaxf(acc[of][2] + b0, 0.f);
        float v3 = fmaxf(acc[of][3] + b1, 0.f);
        uint32_t p0 = packh2(v0, v1), p1 = packh2(v2, v3);
        if (of < 4) {
            *(uint32_t*)&g_Qt[rb0 + o] = p0;
            *(uint32_t*)&g_Qt[rb1 + o] = p1;
            sq0 += v0 * v0 + v1 * v1;
            sq1 += v2 * v2 + v3 * v3;
        } else {
            int ok = o - 32;
            *(uint32_t*)&g_Kt[rb0 + ok] = p0;
            *(uint32_t*)&g_Kt[rb1 + ok] = p1;
            sk0 += v0 * v0 + v1 * v1;
            sk1 += v2 * v2 + v3 * v3;
        }
    }
    sq0 += __shfl_xor_sync(0xffffffffu, sq0, 1); sq0 += __shfl_xor_sync(0xffffffffu, sq0, 2);
    sq1 += __shfl_xor_sync(0xffffffffu, sq1, 1); sq1 += __shfl_xor_sync(0xffffffffu, sq1, 2);
    sk0 += __shfl_xor_sync(0xffffffffu, sk0, 1); sk0 += __shfl_xor_sync(0xffffffffu, sk0, 2);
    sk1 += __shfl_xor_sync(0xffffffffu, sk1, 1); sk1 += __shfl_xor_sync(0xffffffffu, sk1, 2);
    if ((lane & 3) == 0) {
        g_Qn[(size_t)b * NN + n0 + row0] = sqrtf(sq0);
        g_Qn[(size_t)b * NN + n0 + row1] = sqrtf(sq1);
        float km = fmaxf(sqrtf(sk0), sqrtf(sk1));
        atomicMax(&g_Kmax[b], __float_as_uint(km));
    }
}

// ---------------- 3) V conv MMA: 128c x 128n tile, cp.async double-buffered k ----
__global__ void __launch_bounds__(256) vconv_kernel()
{
    extern __shared__ __align__(128) unsigned char vsm[];
    const uint32_t sbv = sm_u32(vsm);

    const int tid = threadIdx.x, wid = tid >> 5, lane = tid & 31;
    const int wm = wid >> 2, wn = wid & 3;
    const int n0 = blockIdx.x * 128, c0 = blockIdx.y * 128, b = blockIdx.z;

    auto issue = [&](int kc) {
        const uint32_t sw = sbv + (kc & 1) * 32768;
        const uint32_t sx = sw + 16384;
        #pragma unroll
        for (int l = 0; l < 4; l++) {
            int idx = tid + l * 256;
            int row = idx >> 3, ch = idx & 7;
            cpasync16(tile_addr(sw, row, ch),
                      &g_Wv[(size_t)(c0 + row) * CC + kc * 64 + ch * 8]);
            cpasync16(tile_addr(sx, row, ch),
                      &g_xT[((size_t)b * NN + n0 + row) * CC + kc * 64 + ch * 8]);
        }
        asm volatile("cp.async.commit_group;" ::: "memory");
    };

    float acc[4][4][4] = {};
    issue(0);

    for (int kc = 0; kc < 4; kc++) {
        if (kc + 1 < 4) {
            issue(kc + 1);
            asm volatile("cp.async.wait_group 1;" ::: "memory");
        } else {
            asm volatile("cp.async.wait_group 0;" ::: "memory");
        }
        __syncthreads();

        const uint32_t sw = sbv + (kc & 1) * 32768;
        const uint32_t sx = sw + 16384;
        #pragma unroll
        for (int ks = 0; ks < 4; ks++) {
            uint32_t af[4][4], bf[4][2];
            #pragma unroll
            for (int fm = 0; fm < 4; fm++)
                ldsm_x4(af[fm], tile_addr(sw, wm * 64 + fm * 16 + (lane & 15), ks * 2 + (lane >> 4)));
            #pragma unroll
            for (int fn = 0; fn < 4; fn++) {
                int t = lane & 15;
                ldsm_x2(bf[fn], tile_addr(sx, wn * 32 + fn * 8 + (t & 7), ks * 2 + (t >> 3)));
            }
            #pragma unroll
            for (int fm = 0; fm < 4; fm++)
                #pragma unroll
                for (int fn = 0; fn < 4; fn++)
                    mma16816(acc[fm][fn], af[fm], bf[fn]);
        }
        __syncthreads();
    }

    const int r = lane >> 2, cq = (lane & 3) * 2;
    #pragma unroll
    for (int fm = 0; fm < 4; fm++) {
        #pragma unroll
        for (int fn = 0; fn < 4; fn++) {
            int c = c0 + wm * 64 + fm * 16 + r;
            int n = n0 + wn * 32 + fn * 8 + cq;
            float b0 = g_Beff[64 + c], b1 = g_Beff[64 + c + 8];
            __half2 h0 = __floats2half2_rn(fmaxf(acc[fm][fn][0] + b0, 0.f),
                                           fmaxf(acc[fm][fn][1] + b0, 0.f));
            __half2 h1 = __floats2half2_rn(fmaxf(acc[fm][fn][2] + b1, 0.f),
                                           fmaxf(acc[fm][fn][3] + b1, 0.f));
            *(__half2*)&g_V[((size_t)b * CC + c) * NN + n]     = h0;
            *(__half2*)&g_V[((size_t)b * CC + c + 8) * NN + n] = h1;
        }
    }
}

// ---------------- 4) flash attention (R12 body + Bv prefetch in PV only) ----------------
__global__ void __launch_bounds__(256, 1) flash_kernel(const float* __restrict__ x,
                                                       const float* __restrict__ gamma,
                                                       float* __restrict__ out)
{
    extern __shared__ __align__(128) unsigned char dsm[];
    const uint32_t sb  = sm_u32(dsm);
    const uint32_t sQ  = sb;
    const uint32_t sK0 = sb + 16384;
    const uint32_t sV0 = sb + 49152;

    const int tid = threadIdx.x, wid = tid >> 5, lane = tid & 31;
    const int i0 = blockIdx.x * 128, c0 = blockIdx.y * 128, b = blockIdx.z;

    const char* qsrc = (const char*)(g_Qt + ((size_t)b * NN + i0) * 64);
    const char* ksrc = (const char*)(g_Kt + (size_t)b * NN * 64);
    const char* vsrc = (const char*)(g_V + ((size_t)b * CC + c0) * NN);

    auto issueK = [&](int it) {
        const uint32_t kb = sK0 + (it & 1) * 16384;
        const char* ks = ksrc + (size_t)it * 128 * 128;
        #pragma unroll
        for (int l = 0; l < 2; l++) {
            int idx = tid + l * 256;
            int row = idx >> 2, ch = idx & 3;
            cpasync16(tile_addr(kb, row, ch), ks + (size_t)row * 128 + ch * 16);
        }
    };
    auto issueV = [&](int it) {
        const uint32_t vb = sV0 + (it % 3) * 32768;
        const size_t jb = (size_t)it * 256;
        #pragma unroll
        for (int l = 0; l < 8; l++) {
            int idx = tid + l * 256;
            int row = idx >> 4, ch = idx & 15;
            cpasync16(tile_addr256(vb, row, ch), vsrc + (size_t)row * (NN * 2) + jb + ch * 16);
        }
    };

    #pragma unroll
    for (int l = 0; l < 2; l++) {
        int idx = tid + l * 256;
        int row = idx >> 2, ch = idx & 3;
        cpasync16(tile_addr(sQ, row, ch), qsrc + (size_t)row * 128 + ch * 16);
    }
    issueK(0); issueV(0);
    asm volatile("cp.async.commit_group;" ::: "memory");

    const float kmax = __uint_as_float(g_Kmax[b]);
    const int rrow = lane >> 2;
    const float mi0 = g_Qn[(size_t)b * NN + i0 + wid * 16 + rrow]     * kmax * L2E - 15.f;
    const float mi1 = g_Qn[(size_t)b * NN + i0 + wid * 16 + rrow + 8] * kmax * L2E - 15.f;

    uint32_t qA[2][4];
    const uint32_t bone[2] = { 0x3C003C00u, 0x3C003C00u };
    float oacc[16][4] = {};
    float lacc[4] = {};
    uint32_t pkp[16][2];

    // PV with 1-deep Bv double-buffer (ldsm for cp+1 issues before cp's MMAs)
    auto doPV = [&](uint32_t vb) {
        const int vrow = (lane & 7) + ((lane >> 4) << 3);
        #pragma unroll
        for (int ks = 0; ks < 8; ks++) {
            uint32_t A[4] = { pkp[2 * ks][0], pkp[2 * ks][1], pkp[2 * ks + 1][0], pkp[2 * ks + 1][1] };
            const int vch = ks * 2 + ((lane >> 3) & 1);
            mma16816(lacc, A, bone);
            uint32_t B0[4], B1[4];
            ldsm_x4(B0, tile_addr256(vb, vrow, vch));
            #pragma unroll
            for (int cp = 0; cp < 8; cp += 2) {
                if (cp + 1 < 8)
                    ldsm_x4(B1, tile_addr256(vb, (cp + 1) * 16 + vrow, vch));
                mma16816(oacc[2 * cp],     A, B0);
                mma16816(oacc[2 * cp + 1], A, B0 + 2);
                if (cp + 2 < 8)
                    ldsm_x4(B0, tile_addr256(vb, (cp + 2) * 16 + vrow, vch));
                mma16816(oacc[2 * cp + 2], A, B1);
                mma16816(oacc[2 * cp + 3], A, B1 + 2);
            }
        }
    };

    for (int it = 0; it < 32; it++) {
        asm volatile("cp.async.wait_group 0;" ::: "memory");
        __syncthreads();

        if (it == 0) {
            #pragma unroll
            for (int ck = 0; ck < 2; ck++)
                ldsm_x4(qA[ck], tile_addr(sQ, wid * 16 + (lane & 15), ck * 2 + (lane >> 4)));
        }

        if (it + 1 < 32) {
            issueK(it + 1); issueV(it + 1);
            asm volatile("cp.async.commit_group;" ::: "memory");
        }

        if (it > 0)
            doPV(sV0 + ((it - 1) % 3) * 32768);

        const uint32_t kb = sK0 + (it & 1) * 16384;
        float sacc[16][4];
        #pragma unroll
        for (int n = 0; n < 16; n++) {
            uint32_t Bh[4];
            ldsm_x4(Bh, tile_addr(kb, n * 8 + (lane & 7), (lane >> 3) & 3));
            mma16816z(sacc[n], qA[0], Bh);
            mma16816 (sacc[n], qA[1], Bh + 2);
        }

        #pragma unroll
        for (int n = 0; n < 16; n++) {
            uint32_t a0 = packh2(fmaf(sacc[n][0], L2E, -mi0), fmaf(sacc[n][1], L2E, -mi0));
            uint32_t a1 = packh2(fmaf(sacc[n][2], L2E, -mi1), fmaf(sacc[n][3], L2E, -mi1));
            pkp[n][0] = ex2h2(a0);
            pkp[n][1] = ex2h2(a1);
        }
    }

    doPV(sV0 + (31 % 3) * 32768);

    const float g = gamma[0];
    const float il0 = g / fmaxf(lacc[0], 1e-25f);
    const float il1 = g / fmaxf(lacc[2], 1e-25f);
    const int r = lane >> 2, q = lane & 3;
    #pragma unroll
    for (int n = 0; n < 16; n++) {
        #pragma unroll
        for (int e = 0; e < 4; e++) {
            int c = c0 + n * 8 + q * 2 + (e & 1);
            int i = i0 + wid * 16 + r + (e >> 1) * 8;
            size_t off = ((size_t)b * CC + c) * NN + i;
            out[off] = oacc[n][e] * ((e < 2) ? il0 : il1) + x[off];
        }
    }
}

// ---------------- launch ----------------
extern "C" void kernel_launch(void* const* d_in, const int* in_sizes, int n_in,
                              void* d_out, int out_size)
{
    const float* x     = (const float*)d_in[0];
    const float* wq    = (const float*)d_in[1];
    const float* bq    = (const float*)d_in[2];
    const float* gq    = (const float*)d_in[3];
    const float* betaq = (const float*)d_in[4];
    const float* mq    = (const float*)d_in[5];
    const float* vq    = (const float*)d_in[6];
    const float* wk    = (const float*)d_in[7];
    const float* bk    = (const float*)d_in[8];
    const float* gk    = (const float*)d_in[9];
    const float* betak = (const float*)d_in[10];
    const float* mk    = (const float*)d_in[11];
    const float* vk    = (const float*)d_in[12];
    const float* wv    = (const float*)d_in[13];
    const float* bv    = (const float*)d_in[14];
    const float* gv    = (const float*)d_in[15];
    const float* betav = (const float*)d_in[16];
    const float* mv    = (const float*)d_in[17];
    const float* vv    = (const float*)d_in[18];
    const float* gamma = (const float*)d_in[19];
    float* out = (float*)d_out;

    cudaFuncSetAttribute(qkconv_kernel, cudaFuncAttributeMaxDynamicSharedMemorySize, 83200);
    cudaFuncSetAttribute(vconv_kernel,  cudaFuncAttributeMaxDynamicSharedMemorySize, 65536);
    cudaFuncSetAttribute(flash_kernel,  cudaFuncAttributeMaxDynamicSharedMemorySize, 147456);

    fold_kernel<<<320, 256>>>(wq, bq, gq, betaq, mq, vq,
                              wk, bk, gk, betak, mk, vk,
                              wv, bv, gv, betav, mv, vv);

    qkconv_kernel<<<dim3(NN / 128, BB), 256, 83200>>>(x);

    vconv_kernel<<<dim3(NN / 128, CC / 128, BB), 256, 65536>>>();

    flash_kernel<<<dim3(NN / 128, 2, BB), 256, 147456>>>(x, gamma, out);
}